// round 6
// baseline (speedup 1.0000x reference)
#include <cuda_runtime.h>
#include <cuda_bf16.h>
#include <cstdint>

// ---------------------------------------------------------------------------
// MHA without softmax, fully folded:
//   out[b] = q[b] @ G_b + c_b,  G_b = W_q · blockdiag(M_b) · W_o,
//   M_b = K_b^T V_b / sqrt(dk)   (per-head 64x64)
// Big GEMMs (bf16 hi/lo split, K=1536, 3-segment schedule): Kp, Vp, G, final.
// B=2, S=2048, D=768, H=12, dk=64.
// ---------------------------------------------------------------------------

#define D_MODEL 768
#define SEQ     2048
#define BATCH   2
#define NTOK    (BATCH*SEQ)          // 4096
#define NHEAD   12
#define DK      64
#define BHTOT   (BATCH*NHEAD)        // 24
#define NCHUNK  32
#define CHUNK_T (SEQ/NCHUNK)         // 64
#define SCALE   0.125f
#define NEGV    (-1000000000.0f)

#define GK2     1536                 // split K: [hi | lo]
#define BK      32
#define SEGSTEP (D_MODEL/BK)         // 24
#define NKSTEP  (3*SEGSTEP)          // 72
#define STAGES  3
#define SM_ABYTES 8192               // 128 rows * 64B
#define SM_BBYTES 8192               // 128 rows * 64B
#define STAGE_BYTES (SM_ABYTES + SM_BBYTES)

// Scratch (allocation-free; __device__ globals are zero-initialized)
__device__ float g_Kp[NTOK*D_MODEL];
__device__ float g_Vp[NTOK*D_MODEL];
__device__ float g_Mpart[BHTOT*NCHUNK*DK*DK];
__device__ float g_M[BHTOT*DK*DK];
__device__ float g_T[2*D_MODEL*D_MODEL];      // [b*768+i][n]
__device__ float g_G[2*D_MODEL*D_MODEL];      // [b*768+i][m]
__device__ float g_cvec[2*D_MODEL];
__device__ float g_zero[D_MODEL];
__device__ __nv_bfloat16 g_Qext[(size_t)NTOK*GK2];
__device__ __nv_bfloat16 g_Aext[(size_t)NTOK*GK2];
__device__ __nv_bfloat16 g_Text[(size_t)2*D_MODEL*GK2];
__device__ __nv_bfloat16 g_Wext[(size_t)D_MODEL*GK2];
__device__ __nv_bfloat16 g_Gext[(size_t)2*D_MODEL*GK2];

// ---------------------------------------------------------------------------
// PTX helpers (generic sm_80+ ISA only)
// ---------------------------------------------------------------------------
__device__ __forceinline__ uint32_t smem_u32(const void* p) {
    uint32_t a;
    asm("{ .reg .u64 t; cvta.to.shared.u64 t, %1; cvt.u32.u64 %0, t; }" : "=r"(a) : "l"(p));
    return a;
}
__device__ __forceinline__ void cp16(uint32_t saddr, const void* g) {
    asm volatile("cp.async.cg.shared.global [%0], [%1], 16;" :: "r"(saddr), "l"(g));
}
#define CP_COMMIT() asm volatile("cp.async.commit_group;" ::: "memory")
#define CP_WAIT1()  asm volatile("cp.async.wait_group 1;" ::: "memory")

__device__ __forceinline__ void ldsm4(uint32_t* r, uint32_t addr) {
    asm volatile("ldmatrix.sync.aligned.m8n8.x4.shared.b16 {%0,%1,%2,%3}, [%4];"
                 : "=r"(r[0]), "=r"(r[1]), "=r"(r[2]), "=r"(r[3]) : "r"(addr));
}
__device__ __forceinline__ void mma16816(float* c, const uint32_t* a,
                                         uint32_t b0, uint32_t b1) {
    asm volatile(
        "mma.sync.aligned.m16n8k16.row.col.f32.bf16.bf16.f32 "
        "{%0,%1,%2,%3}, {%4,%5,%6,%7}, {%8,%9}, {%0,%1,%2,%3};"
        : "+f"(c[0]), "+f"(c[1]), "+f"(c[2]), "+f"(c[3])
        : "r"(a[0]), "r"(a[1]), "r"(a[2]), "r"(a[3]), "r"(b0), "r"(b1));
}
__device__ __forceinline__ uint32_t swz(int r, int c) {
    return (uint32_t)(r * 64 + ((c ^ ((r >> 1) & 3)) << 4));
}

// ---------------------------------------------------------------------------
// Conversions: fp32 -> bf16 [hi | lo] split, K=1536
// ---------------------------------------------------------------------------
__global__ __launch_bounds__(256) void convert_act(
    const float* __restrict__ in, __nv_bfloat16* __restrict__ out, int total)
{
    int idx = blockIdx.x * 256 + threadIdx.x;
    if (idx >= total) return;
    int r = idx / D_MODEL, c = idx - r * D_MODEL;
    float a = in[idx];
    __nv_bfloat16 hi = __float2bfloat16_rn(a);
    __nv_bfloat16 lo = __float2bfloat16_rn(a - __bfloat162float(hi));
    size_t ro = (size_t)r * GK2;
    out[ro + c]       = hi;
    out[ro + 768 + c] = lo;
}

// W [768k,768n] (k-major) -> Wext [768 n-rows][1536] = [hi | lo]
__global__ __launch_bounds__(256) void convert_w(
    const float* __restrict__ W, __nv_bfloat16* __restrict__ out)
{
    __shared__ float t[32][33];
    const int k0 = blockIdx.x * 32, n0 = blockIdx.y * 32;
    const int tx = threadIdx.x & 31, ty = threadIdx.x >> 5;
    #pragma unroll
    for (int i = 0; i < 32; i += 8)
        t[ty + i][tx] = W[(size_t)(k0 + ty + i) * D_MODEL + n0 + tx];
    __syncthreads();
    #pragma unroll
    for (int i = 0; i < 32; i += 8) {
        const int n = n0 + ty + i, k = k0 + tx;
        const float w = t[tx][ty + i];            // = W[k][n]
        __nv_bfloat16 hi = __float2bfloat16_rn(w);
        __nv_bfloat16 lo = __float2bfloat16_rn(w - __bfloat162float(hi));
        size_t ro = (size_t)n * GK2;
        out[ro + k]       = hi;
        out[ro + 768 + k] = lo;
    }
}

// ---------------------------------------------------------------------------
// HMMA GEMM: C[rows,768] = A[rows,1536] (x) B[768,1536] + bias
// 3-segment split schedule: (A_hi,B_hi), (A_hi,B_lo), (A_lo,B_hi).
// 128x128 CTA tile, 8 warps (2x4), 64x32 warp tile, BK=32, 3-stage cp.async.
// B/bias may be batch-strided (batch = row/2048).
// ---------------------------------------------------------------------------
__global__ __launch_bounds__(256, 2) void gemm_hmma(
    const __nv_bfloat16* __restrict__ A,
    const __nv_bfloat16* __restrict__ B, size_t bStride,
    const float* __restrict__ bias, int biasStride,
    float* __restrict__ C)
{
    __shared__ __align__(1024) char smem[STAGES * STAGE_BYTES];
    const int tid  = threadIdx.x;
    const int lane = tid & 31, wid = tid >> 5;
    const int wm = wid >> 2, wn = wid & 3;          // 2 x 4 warps
    const int rowBase = blockIdx.y * 128;
    const int colBase = blockIdx.x * 128;
    const int batch = rowBase >> 11;                 // rows/2048
    const uint32_t sbase = smem_u32(smem);

    const __nv_bfloat16* Ag = A + (size_t)rowBase * GK2;
    const __nv_bfloat16* Bg = B + (size_t)batch * bStride + (size_t)colBase * GK2;
    const float* bp = bias + (size_t)batch * biasStride;

    const int lr = tid >> 2;      // 0..63: rows lr and lr+64
    const int ac = tid & 3;       // 16B chunk in 64B row

    float acc[4][4][4];
    #pragma unroll
    for (int mi = 0; mi < 4; mi++)
        #pragma unroll
        for (int j = 0; j < 4; j++)
            #pragma unroll
            for (int e = 0; e < 4; e++) acc[mi][j][e] = 0.0f;

    // per-kstep global k offsets for the 3-segment schedule
    #define KOFF_A(ks) (((ks) >= 2*SEGSTEP ? 768 : 0) + ((ks) % SEGSTEP) * BK)
    #define KOFF_B(ks) ((((ks) >= SEGSTEP && (ks) < 2*SEGSTEP) ? 768 : 0) + ((ks) % SEGSTEP) * BK)

    // prologue: stages 0,1
    #pragma unroll
    for (int s = 0; s < STAGES - 1; s++) {
        const int ka = KOFF_A(s), kb = KOFF_B(s);
        const uint32_t sa = sbase + s * STAGE_BYTES;
        const uint32_t sb = sa + SM_ABYTES;
        cp16(sa + swz(lr, ac),      Ag + (size_t)lr * GK2 + ka + ac * 8);
        cp16(sa + swz(lr + 64, ac), Ag + (size_t)(lr + 64) * GK2 + ka + ac * 8);
        cp16(sb + swz(lr, ac),      Bg + (size_t)lr * GK2 + kb + ac * 8);
        cp16(sb + swz(lr + 64, ac), Bg + (size_t)(lr + 64) * GK2 + kb + ac * 8);
        CP_COMMIT();
    }

    const int flr = lane & 15;
    const int flc = lane >> 4;

    for (int ks = 0; ks < NKSTEP; ks++) {
        CP_WAIT1();
        __syncthreads();

        if (ks + STAGES - 1 < NKSTEP) {
            const int kn = ks + STAGES - 1;
            const int s  = kn % STAGES;
            const int ka = KOFF_A(kn), kb = KOFF_B(kn);
            const uint32_t sa = sbase + s * STAGE_BYTES;
            const uint32_t sb = sa + SM_ABYTES;
            cp16(sa + swz(lr, ac),      Ag + (size_t)lr * GK2 + ka + ac * 8);
            cp16(sa + swz(lr + 64, ac), Ag + (size_t)(lr + 64) * GK2 + ka + ac * 8);
            cp16(sb + swz(lr, ac),      Bg + (size_t)lr * GK2 + kb + ac * 8);
            cp16(sb + swz(lr + 64, ac), Bg + (size_t)(lr + 64) * GK2 + kb + ac * 8);
            CP_COMMIT();
        }

        const uint32_t sa = sbase + (ks % STAGES) * STAGE_BYTES;
        const uint32_t sb = sa + SM_ABYTES;
        #pragma unroll
        for (int kh = 0; kh < 2; kh++) {
            uint32_t afr[4][4], bfr[2][4];
            const int cc = kh * 2 + flc;
            #pragma unroll
            for (int mi = 0; mi < 4; mi++)
                ldsm4(afr[mi], sa + swz(wm * 64 + mi * 16 + flr, cc));
            #pragma unroll
            for (int ni = 0; ni < 2; ni++)
                ldsm4(bfr[ni], sb + swz(wn * 32 + ni * 16 + flr, cc));
            #pragma unroll
            for (int mi = 0; mi < 4; mi++)
                #pragma unroll
                for (int ni = 0; ni < 2; ni++)
                    #pragma unroll
                    for (int nn = 0; nn < 2; nn++)
                        mma16816(acc[mi][ni * 2 + nn], afr[mi],
                                 bfr[ni][nn], bfr[ni][nn + 2]);
        }
    }

    // epilogue
    #pragma unroll
    for (int mi = 0; mi < 4; mi++) {
        const int row0 = rowBase + wm * 64 + mi * 16 + (lane >> 2);
        #pragma unroll
        for (int j = 0; j < 4; j++) {
            const int col = colBase + wn * 32 + j * 8 + (lane & 3) * 2;
            const float2 bv = *(const float2*)(bp + col);
            float2 o0, o1;
            o0.x = acc[mi][j][0] + bv.x; o0.y = acc[mi][j][1] + bv.y;
            o1.x = acc[mi][j][2] + bv.x; o1.y = acc[mi][j][3] + bv.y;
            *(float2*)(C + (size_t)row0 * D_MODEL + col) = o0;
            *(float2*)(C + (size_t)(row0 + 8) * D_MODEL + col) = o1;
        }
    }
}

// ---------------------------------------------------------------------------
// M = K^T V / sqrt(dk), per (b,h), chunked over t
// ---------------------------------------------------------------------------
__global__ __launch_bounds__(256) void kv_partial_kernel()
{
    const int chunk = blockIdx.x;
    const int bh    = blockIdx.y;
    const int b = bh / NHEAD, h = bh % NHEAD;
    const int tid = threadIdx.x;
    const int tx = tid & 15, ty = tid >> 4;

    __shared__ float ks[8][64];
    __shared__ float vs[8][64];

    const int rowBase = b * SEQ + chunk * CHUNK_T;
    const int colOff  = h * DK;

    const int li = tid * 2;
    const int lr = li >> 6;
    const int lc = li & 63;

    float acc[4][4];
    #pragma unroll
    for (int i = 0; i < 4; i++)
        #pragma unroll
        for (int j = 0; j < 4; j++) acc[i][j] = 0.0f;

    for (int tt = 0; tt < CHUNK_T; tt += 8) {
        const size_t off = (size_t)(rowBase + tt + lr) * D_MODEL + colOff + lc;
        const float2 k2 = *(const float2*)(g_Kp + off);
        const float2 v2 = *(const float2*)(g_Vp + off);
        __syncthreads();
        ks[lr][lc] = k2.x; ks[lr][lc + 1] = k2.y;
        vs[lr][lc] = v2.x; vs[lr][lc + 1] = v2.y;
        __syncthreads();

        #pragma unroll
        for (int r = 0; r < 8; r++) {
            const float a0 = ks[r][ty * 4 + 0];
            const float a1 = ks[r][ty * 4 + 1];
            const float a2 = ks[r][ty * 4 + 2];
            const float a3 = ks[r][ty * 4 + 3];
            const float b0 = vs[r][tx * 4 + 0];
            const float b1 = vs[r][tx * 4 + 1];
            const float b2 = vs[r][tx * 4 + 2];
            const float b3 = vs[r][tx * 4 + 3];
            acc[0][0] += a0 * b0; acc[0][1] += a0 * b1; acc[0][2] += a0 * b2; acc[0][3] += a0 * b3;
            acc[1][0] += a1 * b0; acc[1][1] += a1 * b1; acc[1][2] += a1 * b2; acc[1][3] += a1 * b3;
            acc[2][0] += a2 * b0; acc[2][1] += a2 * b1; acc[2][2] += a2 * b2; acc[2][3] += a2 * b3;
            acc[3][0] += a3 * b0; acc[3][1] += a3 * b1; acc[3][2] += a3 * b2; acc[3][3] += a3 * b3;
        }
    }

    float* mp = g_Mpart + ((size_t)bh * NCHUNK + chunk) * DK * DK;
    #pragma unroll
    for (int i = 0; i < 4; i++)
        #pragma unroll
        for (int j = 0; j < 4; j++)
            mp[(ty * 4 + i) * DK + tx * 4 + j] = acc[i][j];
}

__global__ __launch_bounds__(256) void kv_reduce_kernel()
{
    const int bh = blockIdx.x;
    for (int e = threadIdx.x; e < DK * DK; e += 256) {
        float s = 0.0f;
        #pragma unroll
        for (int c = 0; c < NCHUNK; c++)
            s += g_Mpart[((size_t)bh * NCHUNK + c) * DK * DK + e];
        g_M[(size_t)bh * DK * DK + e] = s * SCALE;
    }
}

// ---------------------------------------------------------------------------
// T_b[i][h*64+j] = sum_l W_q[i][h*64+l] * M_b[h][l][j].  Grid (24 bh, 12 itiles)
// ---------------------------------------------------------------------------
__global__ __launch_bounds__(256) void t_kernel(const float* __restrict__ w_q)
{
    const int bh = blockIdx.x;
    const int b = bh / NHEAD, h = bh % NHEAD;
    const int i0 = blockIdx.y * 64;
    const int tid = threadIdx.x;

    __shared__ float Ms[DK][DK];
    __shared__ float Ws[DK][DK];

    for (int i = tid; i < DK * DK; i += 256) {
        Ms[i >> 6][i & 63] = g_M[(size_t)bh * DK * DK + i];
        Ws[i >> 6][i & 63] = w_q[(size_t)(i0 + (i >> 6)) * D_MODEL + h * DK + (i & 63)];
    }
    __syncthreads();

    const int c  = tid & 63;
    const int rg = tid >> 6;
    for (int r = rg * 16; r < rg * 16 + 16; r++) {
        float acc = 0.0f;
        #pragma unroll 16
        for (int l = 0; l < DK; l++) acc += Ws[r][l] * Ms[l][c];
        g_T[(size_t)(b * D_MODEL + i0 + r) * D_MODEL + h * DK + c] = acc;
    }
}

// cvec_b = b_o + (b_q · BD(M_b)) @ W_o.  Grid 2.
__global__ __launch_bounds__(256) void cvec_kernel(
    const float* __restrict__ b_q, const float* __restrict__ w_o,
    const float* __restrict__ b_o)
{
    const int b = blockIdx.x;
    const int tid = threadIdx.x;
    __shared__ float bqM[D_MODEL];

    for (int n = tid; n < D_MODEL; n += 256) {
        const int h = n >> 6, j = n & 63;
        float s = 0.0f;
        #pragma unroll 16
        for (int i = 0; i < DK; i++)
            s += b_q[h * DK + i] * g_M[(size_t)(b * NHEAD + h) * DK * DK + i * DK + j];
        bqM[n] = s;
    }
    __syncthreads();

    for (int m = tid; m < D_MODEL; m += 256) {
        float s = b_o[m];
        for (int n = 0; n < D_MODEL; n++)
            s += bqM[n] * w_o[(size_t)n * D_MODEL + m];
        g_cvec[b * D_MODEL + m] = s;
    }
}

// ---------------------------------------------------------------------------
// Exact mask handling, applied directly to out (projected through W_o).
// All-ones mask => pure scan, no work.
// ---------------------------------------------------------------------------
__global__ __launch_bounds__(256) void mask_correction_kernel(
    const int* __restrict__ mask, const float* __restrict__ q,
    const float* __restrict__ w_q, const float* __restrict__ b_q,
    const float* __restrict__ w_o, float* __restrict__ out)
{
    const int s = blockIdx.x;
    const int* mrow = mask + (size_t)s * SEQ;
    for (int t = threadIdx.x; t < SEQ; t += 256) {
        if (mrow[t] == 0) {
            for (int b = 0; b < BATCH; b++) {
                const float* qrow = q + (size_t)(b * SEQ + s) * D_MODEL;
                const float* krow = g_Kp + (size_t)(b * SEQ + t) * D_MODEL;
                const float* vrow = g_Vp + (size_t)(b * SEQ + t) * D_MODEL;
                float* orow = out + (size_t)(b * SEQ + s) * D_MODEL;
                for (int h = 0; h < NHEAD; h++) {
                    float raw = 0.0f;
                    for (int l = 0; l < DK; l++) {
                        float qp = b_q[h * DK + l];
                        for (int i = 0; i < D_MODEL; i++)
                            qp += qrow[i] * w_q[(size_t)i * D_MODEL + h * DK + l];
                        raw += qp * krow[h * DK + l];
                    }
                    const float delta = NEGV - raw * SCALE;
                    for (int m = 0; m < D_MODEL; m++) {
                        float pv = 0.0f;
                        for (int j = 0; j < DK; j++)
                            pv += vrow[h * DK + j] * w_o[(size_t)(h * DK + j) * D_MODEL + m];
                        atomicAdd(&orow[m], delta * pv);
                    }
                }
            }
        }
    }
}

// ---------------------------------------------------------------------------
extern "C" void kernel_launch(void* const* d_in, const int* in_sizes, int n_in,
                              void* d_out, int out_size)
{
    const float* q    = (const float*)d_in[0];
    const float* k    = (const float*)d_in[1];
    const float* v    = (const float*)d_in[2];
    const int*   mask = (const int*)  d_in[3];
    const float* w_q  = (const float*)d_in[4];
    const float* b_q  = (const float*)d_in[5];
    const float* w_k  = (const float*)d_in[6];
    const float* b_k  = (const float*)d_in[7];
    const float* w_v  = (const float*)d_in[8];
    const float* b_v  = (const float*)d_in[9];
    const float* w_o  = (const float*)d_in[10];
    const float* b_o  = (const float*)d_in[11];
    float* out = (float*)d_out;

    float *Kp, *Vp, *T, *G, *cvec, *zero;
    __nv_bfloat16 *Qext, *Aext, *Text, *Wext, *Gext;
    cudaGetSymbolAddress((void**)&Kp,   g_Kp);
    cudaGetSymbolAddress((void**)&Vp,   g_Vp);
    cudaGetSymbolAddress((void**)&T,    g_T);
    cudaGetSymbolAddress((void**)&G,    g_G);
    cudaGetSymbolAddress((void**)&cvec, g_cvec);
    cudaGetSymbolAddress((void**)&zero, g_zero);
    cudaGetSymbolAddress((void**)&Qext, g_Qext);
    cudaGetSymbolAddress((void**)&Aext, g_Aext);
    cudaGetSymbolAddress((void**)&Text, g_Text);
    cudaGetSymbolAddress((void**)&Wext, g_Wext);
    cudaGetSymbolAddress((void**)&Gext, g_Gext);

    const int actTotal = NTOK * D_MODEL;
    const int actBlocks = (actTotal + 255) / 256;
    const int tTotal = 2 * D_MODEL * D_MODEL;
    const int tBlocks = (tTotal + 255) / 256;
    const dim3 cwg(D_MODEL / 32, D_MODEL / 32);          // (24,24)
    const dim3 ggBig(D_MODEL / 128, NTOK / 128);          // (6, 32)
    const dim3 ggG(D_MODEL / 128, 2 * D_MODEL / 128);     // (6, 12)

    // K projection
    convert_w<<<cwg, 256>>>(w_k, Wext);
    convert_act<<<actBlocks, 256>>>(k, Aext, actTotal);
    gemm_hmma<<<ggBig, 256>>>(Aext, Wext, 0, b_k, 0, Kp);

    // V projection
    convert_w<<<cwg, 256>>>(w_v, Wext);
    convert_act<<<actBlocks, 256>>>(v, Aext, actTotal);
    gemm_hmma<<<ggBig, 256>>>(Aext, Wext, 0, b_v, 0, Vp);

    // q conversion (for the final GEMM)
    convert_act<<<actBlocks, 256>>>(q, Qext, actTotal);

    // M = K^T V / sqrt(dk)
    kv_partial_kernel<<<dim3(NCHUNK, BHTOT), 256>>>();
    kv_reduce_kernel<<<BHTOT, 256>>>();

    // T_b = W_q * BD(M_b);  G_b = T_b @ W_o  (1536-row split GEMM)
    t_kernel<<<dim3(BHTOT, D_MODEL / 64), 256>>>(w_q);
    convert_act<<<tBlocks, 256>>>(T, Text, tTotal);
    convert_w<<<cwg, 256>>>(w_o, Wext);
    gemm_hmma<<<ggG, 256>>>(Text, Wext, 0, zero, 0, G);

    // Gext per batch (n-major split), cvec
    convert_w<<<cwg, 256>>>(G, Gext);
    convert_w<<<cwg, 256>>>(G + (size_t)D_MODEL * D_MODEL,
                            Gext + (size_t)D_MODEL * GK2);
    cvec_kernel<<<2, 256>>>(b_q, w_o, b_o);

    // out[b] = q[b] @ G_b + cvec_b
    gemm_hmma<<<ggBig, 256>>>(Qext, Gext, (size_t)D_MODEL * GK2, cvec, D_MODEL, out);

    // exact mask handling (no-op for all-ones mask)
    mask_correction_kernel<<<SEQ, 256>>>(mask, q, w_q, b_q, w_o, out);
}

// round 7
// speedup vs baseline: 1.2124x; 1.2124x over previous
#include <cuda_runtime.h>
#include <cuda_bf16.h>
#include <cstdint>

// ---------------------------------------------------------------------------
// MHA without softmax, fully folded:
//   out[b] = q[b] @ G_b + c_b,  G_b = W_q · blockdiag(M_b) · W_o,
//   M_b = K_b^T V_b / sqrt(dk)   (per-head 64x64)
// GEMMs (bf16 [hi|lo] K=1536, 3-segment schedule): Kp, Vp, G(0.375), final.
// GEMM geometry = round-4 proven config (128x64 tile, 32x32 warp tiles).
// B=2, S=2048, D=768, H=12, dk=64.
// ---------------------------------------------------------------------------

#define D_MODEL 768
#define SEQ     2048
#define BATCH   2
#define NTOK    (BATCH*SEQ)          // 4096
#define NHEAD   12
#define DK      64
#define BHTOT   (BATCH*NHEAD)        // 24
#define NCHUNK  32
#define CHUNK_T (SEQ/NCHUNK)         // 64
#define SCALE   0.125f
#define NEGV    (-1000000000.0f)

#define GK2     1536                 // split K: [hi | lo]
#define BK      32
#define SEGSTEP (D_MODEL/BK)         // 24
#define NKSTEP  (3*SEGSTEP)          // 72
#define STAGES  3
#define SM_ABYTES 8192               // 128 rows * 64B
#define SM_BBYTES 4096               // 64 rows * 64B
#define STAGE_BYTES (SM_ABYTES + SM_BBYTES)

// Scratch (allocation-free)
__device__ float g_Kp[NTOK*D_MODEL];
__device__ float g_Vp[NTOK*D_MODEL];
__device__ float g_Mpart[BHTOT*NCHUNK*DK*DK];
__device__ float g_M[BHTOT*DK*DK];
__device__ float g_T[2*D_MODEL*D_MODEL];
__device__ float g_G[2*D_MODEL*D_MODEL];
__device__ float g_cvec[2*D_MODEL];
__device__ float g_zero[D_MODEL];
__device__ __nv_bfloat16 g_Qext[(size_t)NTOK*GK2];
__device__ __nv_bfloat16 g_Aext[(size_t)NTOK*GK2];
__device__ __nv_bfloat16 g_Text[(size_t)2*D_MODEL*GK2];
__device__ __nv_bfloat16 g_Wext[(size_t)D_MODEL*GK2];
__device__ __nv_bfloat16 g_Gext[(size_t)2*D_MODEL*GK2];

// ---------------------------------------------------------------------------
// PTX helpers (generic sm_80+ ISA only)
// ---------------------------------------------------------------------------
__device__ __forceinline__ uint32_t smem_u32(const void* p) {
    uint32_t a;
    asm("{ .reg .u64 t; cvta.to.shared.u64 t, %1; cvt.u32.u64 %0, t; }" : "=r"(a) : "l"(p));
    return a;
}
__device__ __forceinline__ void cp16(uint32_t saddr, const void* g) {
    asm volatile("cp.async.cg.shared.global [%0], [%1], 16;" :: "r"(saddr), "l"(g));
}
#define CP_COMMIT() asm volatile("cp.async.commit_group;" ::: "memory")
#define CP_WAIT1()  asm volatile("cp.async.wait_group 1;" ::: "memory")

__device__ __forceinline__ void ldsm4(uint32_t* r, uint32_t addr) {
    asm volatile("ldmatrix.sync.aligned.m8n8.x4.shared.b16 {%0,%1,%2,%3}, [%4];"
                 : "=r"(r[0]), "=r"(r[1]), "=r"(r[2]), "=r"(r[3]) : "r"(addr));
}
__device__ __forceinline__ void mma16816(float* c, const uint32_t* a,
                                         uint32_t b0, uint32_t b1) {
    asm volatile(
        "mma.sync.aligned.m16n8k16.row.col.f32.bf16.bf16.f32 "
        "{%0,%1,%2,%3}, {%4,%5,%6,%7}, {%8,%9}, {%0,%1,%2,%3};"
        : "+f"(c[0]), "+f"(c[1]), "+f"(c[2]), "+f"(c[3])
        : "r"(a[0]), "r"(a[1]), "r"(a[2]), "r"(a[3]), "r"(b0), "r"(b1));
}
__device__ __forceinline__ uint32_t swz(int r, int c) {
    return (uint32_t)(r * 64 + ((c ^ ((r >> 1) & 3)) << 4));
}

// ---------------------------------------------------------------------------
// Conversions: fp32 -> bf16 [hi | lo] split, K=1536
// ---------------------------------------------------------------------------
__global__ __launch_bounds__(256) void convert_act(
    const float* __restrict__ in, __nv_bfloat16* __restrict__ out, int total)
{
    int idx = blockIdx.x * 256 + threadIdx.x;
    if (idx >= total) return;
    int r = idx / D_MODEL, c = idx - r * D_MODEL;
    float a = in[idx];
    __nv_bfloat16 hi = __float2bfloat16_rn(a);
    __nv_bfloat16 lo = __float2bfloat16_rn(a - __bfloat162float(hi));
    size_t ro = (size_t)r * GK2;
    out[ro + c]       = hi;
    out[ro + 768 + c] = lo;
}

// W [768k,768n] (k-major) -> Wext [768 n-rows][1536] = [hi | lo]
__global__ __launch_bounds__(256) void convert_w(
    const float* __restrict__ W, __nv_bfloat16* __restrict__ out)
{
    __shared__ float t[32][33];
    const int k0 = blockIdx.x * 32, n0 = blockIdx.y * 32;
    const int tx = threadIdx.x & 31, ty = threadIdx.x >> 5;
    #pragma unroll
    for (int i = 0; i < 32; i += 8)
        t[ty + i][tx] = W[(size_t)(k0 + ty + i) * D_MODEL + n0 + tx];
    __syncthreads();
    #pragma unroll
    for (int i = 0; i < 32; i += 8) {
        const int n = n0 + ty + i, k = k0 + tx;
        const float w = t[tx][ty + i];            // = W[k][n]
        __nv_bfloat16 hi = __float2bfloat16_rn(w);
        __nv_bfloat16 lo = __float2bfloat16_rn(w - __bfloat162float(hi));
        size_t ro = (size_t)n * GK2;
        out[ro + k]       = hi;
        out[ro + 768 + k] = lo;
    }
}

// ---------------------------------------------------------------------------
// HMMA GEMM (round-4 proven geometry):
// C[rows,768] = A[rows,1536] (x) B[768,1536] + bias
// 3-segment schedule: (A_hi,B_hi), (A_hi,B_lo), (A_lo,B_hi).
// 128x64 CTA tile, 8 warps (4x2), 32x32 warp tile, BK=32, 3-stage cp.async.
// B/bias may be batch-strided (batch = rowBase/2048).
// ---------------------------------------------------------------------------
__global__ __launch_bounds__(256, 2) void gemm_hmma(
    const __nv_bfloat16* __restrict__ A,
    const __nv_bfloat16* __restrict__ B, size_t bStride,
    const float* __restrict__ bias, int biasStride,
    float* __restrict__ C)
{
    __shared__ __align__(1024) char smem[STAGES * STAGE_BYTES];
    const int tid  = threadIdx.x;
    const int lane = tid & 31, wid = tid >> 5;
    const int wm = wid & 3, wn = wid >> 2;       // 4 x 2 warps
    const int rowBase = blockIdx.y * 128;
    const int colBase = blockIdx.x * 64;
    const int batch = rowBase >> 11;
    const uint32_t sbase = smem_u32(smem);

    const __nv_bfloat16* Ag = A + (size_t)rowBase * GK2;
    const __nv_bfloat16* Bg = B + (size_t)batch * bStride + (size_t)colBase * GK2;
    const float* bp = bias + (size_t)batch * biasStride;

    const int lr = tid >> 2;      // load row (A: lr and lr+64; B: lr)
    const int ac = tid & 3;       // 16B chunk within 64B row

    float acc[2][4][4];
    #pragma unroll
    for (int mi = 0; mi < 2; mi++)
        #pragma unroll
        for (int j = 0; j < 4; j++)
            #pragma unroll
            for (int e = 0; e < 4; e++) acc[mi][j][e] = 0.0f;

    #define KOFF_A(ks) (((ks) >= 2*SEGSTEP ? 768 : 0) + ((ks) % SEGSTEP) * BK)
    #define KOFF_B(ks) ((((ks) >= SEGSTEP && (ks) < 2*SEGSTEP) ? 768 : 0) + ((ks) % SEGSTEP) * BK)

    // prologue: stages 0,1
    #pragma unroll
    for (int s = 0; s < STAGES - 1; s++) {
        const int ka = KOFF_A(s), kb = KOFF_B(s);
        const uint32_t sa = sbase + s * STAGE_BYTES;
        const uint32_t sb = sa + SM_ABYTES;
        cp16(sa + swz(lr, ac),      Ag + (size_t)lr * GK2 + ka + ac * 8);
        cp16(sa + swz(lr + 64, ac), Ag + (size_t)(lr + 64) * GK2 + ka + ac * 8);
        cp16(sb + swz(lr, ac),      Bg + (size_t)lr * GK2 + kb + ac * 8);
        CP_COMMIT();
    }

    const int flr = lane & 15;
    const int flc = lane >> 4;

    for (int ks = 0; ks < NKSTEP; ks++) {
        CP_WAIT1();
        __syncthreads();

        if (ks + STAGES - 1 < NKSTEP) {
            const int kn = ks + STAGES - 1;
            const int s  = kn % STAGES;
            const int ka = KOFF_A(kn), kb = KOFF_B(kn);
            const uint32_t sa = sbase + s * STAGE_BYTES;
            const uint32_t sb = sa + SM_ABYTES;
            cp16(sa + swz(lr, ac),      Ag + (size_t)lr * GK2 + ka + ac * 8);
            cp16(sa + swz(lr + 64, ac), Ag + (size_t)(lr + 64) * GK2 + ka + ac * 8);
            cp16(sb + swz(lr, ac),      Bg + (size_t)lr * GK2 + kb + ac * 8);
            CP_COMMIT();
        }

        const uint32_t sa = sbase + (ks % STAGES) * STAGE_BYTES;
        const uint32_t sb = sa + SM_ABYTES;
        #pragma unroll
        for (int kh = 0; kh < 2; kh++) {
            uint32_t afr[2][4], bfr[2][4];
            const int cc = kh * 2 + flc;
            #pragma unroll
            for (int mi = 0; mi < 2; mi++)
                ldsm4(afr[mi], sa + swz(wm * 32 + mi * 16 + flr, cc));
            #pragma unroll
            for (int ni = 0; ni < 2; ni++)
                ldsm4(bfr[ni], sb + swz(wn * 32 + ni * 16 + flr, cc));
            #pragma unroll
            for (int mi = 0; mi < 2; mi++)
                #pragma unroll
                for (int ni = 0; ni < 2; ni++)
                    #pragma unroll
                    for (int nn = 0; nn < 2; nn++)
                        mma16816(acc[mi][ni * 2 + nn], afr[mi],
                                 bfr[ni][nn], bfr[ni][nn + 2]);
        }
    }

    // epilogue: +bias, write fp32
    #pragma unroll
    for (int mi = 0; mi < 2; mi++) {
        const int row0 = rowBase + wm * 32 + mi * 16 + (lane >> 2);
        #pragma unroll
        for (int j = 0; j < 4; j++) {
            const int col = colBase + wn * 32 + j * 8 + (lane & 3) * 2;
            const float2 bv = *(const float2*)(bp + col);
            float2 o0, o1;
            o0.x = acc[mi][j][0] + bv.x; o0.y = acc[mi][j][1] + bv.y;
            o1.x = acc[mi][j][2] + bv.x; o1.y = acc[mi][j][3] + bv.y;
            *(float2*)(C + (size_t)row0 * D_MODEL + col) = o0;
            *(float2*)(C + (size_t)(row0 + 8) * D_MODEL + col) = o1;
        }
    }
}

// ---------------------------------------------------------------------------
// M = K^T V / sqrt(dk), per (b,h), chunked over t
// ---------------------------------------------------------------------------
__global__ __launch_bounds__(256) void kv_partial_kernel()
{
    const int chunk = blockIdx.x;
    const int bh    = blockIdx.y;
    const int b = bh / NHEAD, h = bh % NHEAD;
    const int tid = threadIdx.x;
    const int tx = tid & 15, ty = tid >> 4;

    __shared__ float ks[8][64];
    __shared__ float vs[8][64];

    const int rowBase = b * SEQ + chunk * CHUNK_T;
    const int colOff  = h * DK;

    const int li = tid * 2;
    const int lr = li >> 6;
    const int lc = li & 63;

    float acc[4][4];
    #pragma unroll
    for (int i = 0; i < 4; i++)
        #pragma unroll
        for (int j = 0; j < 4; j++) acc[i][j] = 0.0f;

    for (int tt = 0; tt < CHUNK_T; tt += 8) {
        const size_t off = (size_t)(rowBase + tt + lr) * D_MODEL + colOff + lc;
        const float2 k2 = *(const float2*)(g_Kp + off);
        const float2 v2 = *(const float2*)(g_Vp + off);
        __syncthreads();
        ks[lr][lc] = k2.x; ks[lr][lc + 1] = k2.y;
        vs[lr][lc] = v2.x; vs[lr][lc + 1] = v2.y;
        __syncthreads();

        #pragma unroll
        for (int r = 0; r < 8; r++) {
            const float a0 = ks[r][ty * 4 + 0];
            const float a1 = ks[r][ty * 4 + 1];
            const float a2 = ks[r][ty * 4 + 2];
            const float a3 = ks[r][ty * 4 + 3];
            const float b0 = vs[r][tx * 4 + 0];
            const float b1 = vs[r][tx * 4 + 1];
            const float b2 = vs[r][tx * 4 + 2];
            const float b3 = vs[r][tx * 4 + 3];
            acc[0][0] += a0 * b0; acc[0][1] += a0 * b1; acc[0][2] += a0 * b2; acc[0][3] += a0 * b3;
            acc[1][0] += a1 * b0; acc[1][1] += a1 * b1; acc[1][2] += a1 * b2; acc[1][3] += a1 * b3;
            acc[2][0] += a2 * b0; acc[2][1] += a2 * b1; acc[2][2] += a2 * b2; acc[2][3] += a2 * b3;
            acc[3][0] += a3 * b0; acc[3][1] += a3 * b1; acc[3][2] += a3 * b2; acc[3][3] += a3 * b3;
        }
    }

    float* mp = g_Mpart + ((size_t)bh * NCHUNK + chunk) * DK * DK;
    #pragma unroll
    for (int i = 0; i < 4; i++)
        #pragma unroll
        for (int j = 0; j < 4; j++)
            mp[(ty * 4 + i) * DK + tx * 4 + j] = acc[i][j];
}

__global__ __launch_bounds__(256) void kv_reduce_kernel()
{
    const int bh = blockIdx.x;
    for (int e = threadIdx.x; e < DK * DK; e += 256) {
        float s = 0.0f;
        #pragma unroll
        for (int c = 0; c < NCHUNK; c++)
            s += g_Mpart[((size_t)bh * NCHUNK + c) * DK * DK + e];
        g_M[(size_t)bh * DK * DK + e] = s * SCALE;
    }
}

// ---------------------------------------------------------------------------
// T_b[i][h*64+j] = sum_l W_q[i][h*64+l] * M_b[h][l][j].  Grid (24 bh, 12 itiles)
// ---------------------------------------------------------------------------
__global__ __launch_bounds__(256) void t_kernel(const float* __restrict__ w_q)
{
    const int bh = blockIdx.x;
    const int b = bh / NHEAD, h = bh % NHEAD;
    const int i0 = blockIdx.y * 64;
    const int tid = threadIdx.x;

    __shared__ float Ms[DK][DK];
    __shared__ float Ws[DK][DK];

    for (int i = tid; i < DK * DK; i += 256) {
        Ms[i >> 6][i & 63] = g_M[(size_t)bh * DK * DK + i];
        Ws[i >> 6][i & 63] = w_q[(size_t)(i0 + (i >> 6)) * D_MODEL + h * DK + (i & 63)];
    }
    __syncthreads();

    const int c  = tid & 63;
    const int rg = tid >> 6;
    for (int r = rg * 16; r < rg * 16 + 16; r++) {
        float acc = 0.0f;
        #pragma unroll 16
        for (int l = 0; l < DK; l++) acc += Ws[r][l] * Ms[l][c];
        g_T[(size_t)(b * D_MODEL + i0 + r) * D_MODEL + h * DK + c] = acc;
    }
}

// cvec_b = b_o + (b_q · BD(M_b)) @ W_o.  Grid 2.
__global__ __launch_bounds__(256) void cvec_kernel(
    const float* __restrict__ b_q, const float* __restrict__ w_o,
    const float* __restrict__ b_o)
{
    const int b = blockIdx.x;
    const int tid = threadIdx.x;
    __shared__ float bqM[D_MODEL];

    for (int n = tid; n < D_MODEL; n += 256) {
        const int h = n >> 6, j = n & 63;
        float s = 0.0f;
        #pragma unroll 16
        for (int i = 0; i < DK; i++)
            s += b_q[h * DK + i] * g_M[(size_t)(b * NHEAD + h) * DK * DK + i * DK + j];
        bqM[n] = s;
    }
    __syncthreads();

    for (int m = tid; m < D_MODEL; m += 256) {
        float s = b_o[m];
        for (int n = 0; n < D_MODEL; n++)
            s += bqM[n] * w_o[(size_t)n * D_MODEL + m];
        g_cvec[b * D_MODEL + m] = s;
    }
}

// ---------------------------------------------------------------------------
// Exact mask handling, applied directly to out (projected through W_o).
// All-ones mask => pure scan, no work.
// ---------------------------------------------------------------------------
__global__ __launch_bounds__(256) void mask_correction_kernel(
    const int* __restrict__ mask, const float* __restrict__ q,
    const float* __restrict__ w_q, const float* __restrict__ b_q,
    const float* __restrict__ w_o, float* __restrict__ out)
{
    const int s = blockIdx.x;
    const int* mrow = mask + (size_t)s * SEQ;
    for (int t = threadIdx.x; t < SEQ; t += 256) {
        if (mrow[t] == 0) {
            for (int b = 0; b < BATCH; b++) {
                const float* qrow = q + (size_t)(b * SEQ + s) * D_MODEL;
                const float* krow = g_Kp + (size_t)(b * SEQ + t) * D_MODEL;
                const float* vrow = g_Vp + (size_t)(b * SEQ + t) * D_MODEL;
                float* orow = out + (size_t)(b * SEQ + s) * D_MODEL;
                for (int h = 0; h < NHEAD; h++) {
                    float raw = 0.0f;
                    for (int l = 0; l < DK; l++) {
                        float qp = b_q[h * DK + l];
                        for (int i = 0; i < D_MODEL; i++)
                            qp += qrow[i] * w_q[(size_t)i * D_MODEL + h * DK + l];
                        raw += qp * krow[h * DK + l];
                    }
                    const float delta = NEGV - raw * SCALE;
                    for (int m = 0; m < D_MODEL; m++) {
                        float pv = 0.0f;
                        for (int j = 0; j < DK; j++)
                            pv += vrow[h * DK + j] * w_o[(size_t)(h * DK + j) * D_MODEL + m];
                        atomicAdd(&orow[m], delta * pv);
                    }
                }
            }
        }
    }
}

// ---------------------------------------------------------------------------
extern "C" void kernel_launch(void* const* d_in, const int* in_sizes, int n_in,
                              void* d_out, int out_size)
{
    const float* q    = (const float*)d_in[0];
    const float* k    = (const float*)d_in[1];
    const float* v    = (const float*)d_in[2];
    const int*   mask = (const int*)  d_in[3];
    const float* w_q  = (const float*)d_in[4];
    const float* b_q  = (const float*)d_in[5];
    const float* w_k  = (const float*)d_in[6];
    const float* b_k  = (const float*)d_in[7];
    const float* w_v  = (const float*)d_in[8];
    const float* b_v  = (const float*)d_in[9];
    const float* w_o  = (const float*)d_in[10];
    const float* b_o  = (const float*)d_in[11];
    float* out = (float*)d_out;

    float *Kp, *Vp, *T, *G, *cvec, *zero;
    __nv_bfloat16 *Qext, *Aext, *Text, *Wext, *Gext;
    cudaGetSymbolAddress((void**)&Kp,   g_Kp);
    cudaGetSymbolAddress((void**)&Vp,   g_Vp);
    cudaGetSymbolAddress((void**)&T,    g_T);
    cudaGetSymbolAddress((void**)&G,    g_G);
    cudaGetSymbolAddress((void**)&cvec, g_cvec);
    cudaGetSymbolAddress((void**)&zero, g_zero);
    cudaGetSymbolAddress((void**)&Qext, g_Qext);
    cudaGetSymbolAddress((void**)&Aext, g_Aext);
    cudaGetSymbolAddress((void**)&Text, g_Text);
    cudaGetSymbolAddress((void**)&Wext, g_Wext);
    cudaGetSymbolAddress((void**)&Gext, g_Gext);

    const int actTotal = NTOK * D_MODEL;
    const int actBlocks = (actTotal + 255) / 256;
    const int tTotal = 2 * D_MODEL * D_MODEL;
    const int tBlocks = (tTotal + 255) / 256;
    const dim3 cwg(D_MODEL / 32, D_MODEL / 32);          // (24,24)
    const dim3 ggBig(D_MODEL / 64, NTOK / 128);           // (12, 32)
    const dim3 ggG(D_MODEL / 64, 2 * D_MODEL / 128);      // (12, 12)

    // K projection
    convert_w<<<cwg, 256>>>(w_k, Wext);
    convert_act<<<actBlocks, 256>>>(k, Aext, actTotal);
    gemm_hmma<<<ggBig, 256>>>(Aext, Wext, 0, b_k, 0, Kp);

    // V projection
    convert_w<<<cwg, 256>>>(w_v, Wext);
    convert_act<<<actBlocks, 256>>>(v, Aext, actTotal);
    gemm_hmma<<<ggBig, 256>>>(Aext, Wext, 0, b_v, 0, Vp);

    // q conversion (overlaps with V projection chain)
    convert_act<<<actBlocks, 256>>>(q, Qext, actTotal);

    // M = K^T V / sqrt(dk)
    kv_partial_kernel<<<dim3(NCHUNK, BHTOT), 256>>>();
    kv_reduce_kernel<<<BHTOT, 256>>>();

    // T_b = W_q * BD(M_b);  G_b = T_b @ W_o  (1536-row split GEMM)
    t_kernel<<<dim3(BHTOT, D_MODEL / 64), 256>>>(w_q);
    convert_act<<<tBlocks, 256>>>(T, Text, tTotal);
    convert_w<<<cwg, 256>>>(w_o, Wext);
    gemm_hmma<<<ggG, 256>>>(Text, Wext, 0, zero, 0, G);

    // Gext per batch (n-major split), cvec
    convert_w<<<cwg, 256>>>(G, Gext);
    convert_w<<<cwg, 256>>>(G + (size_t)D_MODEL * D_MODEL,
                            Gext + (size_t)D_MODEL * GK2);
    cvec_kernel<<<2, 256>>>(b_q, w_o, b_o);

    // out[b] = q[b] @ G_b + cvec_b
    gemm_hmma<<<ggBig, 256>>>(Qext, Gext, (size_t)D_MODEL * GK2, cvec, D_MODEL, out);

    // exact mask handling (no-op for all-ones mask)
    mask_correction_kernel<<<SEQ, 256>>>(mask, q, w_q, b_q, w_o, out);
}

// round 8
// speedup vs baseline: 1.3534x; 1.1163x over previous
#include <cuda_runtime.h>
#include <cuda_bf16.h>
#include <cstdint>

// ---------------------------------------------------------------------------
// MHA without softmax, fully folded:
//   out[b] = q[b] @ G_b + c_b,  G_b = W_q · blockdiag(M_b) · W_o,
//   M_b = K_b^T V_b / sqrt(dk)   (per-head 64x64)
// GEMMs (bf16 [hi|lo] K=1536, 3-segment schedule):
//   merged KV (8192 rows), G (1536 rows), final (4096 rows).
// GEMM inner loop = round-4 proven config (128x64 tile, 32x32 warp tiles).
// ---------------------------------------------------------------------------

#define D_MODEL 768
#define SEQ     2048
#define BATCH   2
#define NTOK    (BATCH*SEQ)          // 4096
#define NHEAD   12
#define DK      64
#define BHTOT   (BATCH*NHEAD)        // 24
#define NCHUNK  32
#define CHUNK_T (SEQ/NCHUNK)         // 64
#define SCALE   0.125f
#define NEGV    (-1000000000.0f)

#define GK2     1536                 // split K: [hi | lo]
#define BK      32
#define SEGSTEP (D_MODEL/BK)         // 24
#define NKSTEP  (3*SEGSTEP)          // 72
#define STAGES  3
#define SM_ABYTES 8192               // 128 rows * 64B
#define SM_BBYTES 4096               // 64 rows * 64B
#define STAGE_BYTES (SM_ABYTES + SM_BBYTES)

// Scratch (allocation-free)
__device__ float g_KVp[2*NTOK*D_MODEL];       // rows 0..4095 = Kp, 4096.. = Vp
__device__ float g_Mpart[BHTOT*NCHUNK*DK*DK];
__device__ float g_M[BHTOT*DK*DK];
__device__ float g_T[2*D_MODEL*D_MODEL];
__device__ float g_G[2*D_MODEL*D_MODEL];
__device__ float g_cvec[2*D_MODEL];
__device__ float g_zero[D_MODEL];
__device__ float g_biasKV[2*D_MODEL];
__device__ __nv_bfloat16 g_Qext[(size_t)NTOK*GK2];
__device__ __nv_bfloat16 g_Aext[(size_t)2*NTOK*GK2];
__device__ __nv_bfloat16 g_Text[(size_t)2*D_MODEL*GK2];
__device__ __nv_bfloat16 g_Wext[(size_t)2*D_MODEL*GK2];
__device__ __nv_bfloat16 g_Gext[(size_t)2*D_MODEL*GK2];

// ---------------------------------------------------------------------------
// PTX helpers (generic sm_80+ ISA only)
// ---------------------------------------------------------------------------
__device__ __forceinline__ uint32_t smem_u32(const void* p) {
    uint32_t a;
    asm("{ .reg .u64 t; cvta.to.shared.u64 t, %1; cvt.u32.u64 %0, t; }" : "=r"(a) : "l"(p));
    return a;
}
__device__ __forceinline__ void cp16(uint32_t saddr, const void* g) {
    asm volatile("cp.async.cg.shared.global [%0], [%1], 16;" :: "r"(saddr), "l"(g));
}
#define CP_COMMIT() asm volatile("cp.async.commit_group;" ::: "memory")
#define CP_WAIT1()  asm volatile("cp.async.wait_group 1;" ::: "memory")

__device__ __forceinline__ void ldsm4(uint32_t* r, uint32_t addr) {
    asm volatile("ldmatrix.sync.aligned.m8n8.x4.shared.b16 {%0,%1,%2,%3}, [%4];"
                 : "=r"(r[0]), "=r"(r[1]), "=r"(r[2]), "=r"(r[3]) : "r"(addr));
}
__device__ __forceinline__ void mma16816(float* c, const uint32_t* a,
                                         uint32_t b0, uint32_t b1) {
    asm volatile(
        "mma.sync.aligned.m16n8k16.row.col.f32.bf16.bf16.f32 "
        "{%0,%1,%2,%3}, {%4,%5,%6,%7}, {%8,%9}, {%0,%1,%2,%3};"
        : "+f"(c[0]), "+f"(c[1]), "+f"(c[2]), "+f"(c[3])
        : "r"(a[0]), "r"(a[1]), "r"(a[2]), "r"(a[3]), "r"(b0), "r"(b1));
}
__device__ __forceinline__ uint32_t swz(int r, int c) {
    return (uint32_t)(r * 64 + ((c ^ ((r >> 1) & 3)) << 4));
}

// ---------------------------------------------------------------------------
// Conversions: fp32 -> bf16 [hi | lo] split, K=1536
// ---------------------------------------------------------------------------
__global__ __launch_bounds__(256) void convert_act(
    const float* __restrict__ in, __nv_bfloat16* __restrict__ out, int total)
{
    int idx = blockIdx.x * 256 + threadIdx.x;
    if (idx >= total) return;
    int r = idx / D_MODEL, c = idx - r * D_MODEL;
    float a = in[idx];
    __nv_bfloat16 hi = __float2bfloat16_rn(a);
    __nv_bfloat16 lo = __float2bfloat16_rn(a - __bfloat162float(hi));
    size_t ro = (size_t)r * GK2;
    out[ro + c]       = hi;
    out[ro + 768 + c] = lo;
}

// W [768k,768n] (k-major) -> Wext [768 n-rows][1536] = [hi | lo]
// blockIdx.z selects a batch (contiguous 768x768 input, 768x1536 output).
__global__ __launch_bounds__(256) void convert_w(
    const float* __restrict__ W, __nv_bfloat16* __restrict__ out)
{
    W   += (size_t)blockIdx.z * D_MODEL * D_MODEL;
    out += (size_t)blockIdx.z * D_MODEL * GK2;
    __shared__ float t[32][33];
    const int k0 = blockIdx.x * 32, n0 = blockIdx.y * 32;
    const int tx = threadIdx.x & 31, ty = threadIdx.x >> 5;
    #pragma unroll
    for (int i = 0; i < 32; i += 8)
        t[ty + i][tx] = W[(size_t)(k0 + ty + i) * D_MODEL + n0 + tx];
    __syncthreads();
    #pragma unroll
    for (int i = 0; i < 32; i += 8) {
        const int n = n0 + ty + i, k = k0 + tx;
        const float w = t[tx][ty + i];            // = W[k][n]
        __nv_bfloat16 hi = __float2bfloat16_rn(w);
        __nv_bfloat16 lo = __float2bfloat16_rn(w - __bfloat162float(hi));
        size_t ro = (size_t)n * GK2;
        out[ro + k]       = hi;
        out[ro + 768 + k] = lo;
    }
}

// ---------------------------------------------------------------------------
// HMMA GEMM (round-4 proven inner loop):
// C[rows,768] = A[rows,1536] (x) B[768,1536] + bias
// 3-segment schedule: (A_hi,B_hi), (A_hi,B_lo), (A_lo,B_hi).
// 128x64 CTA tile, 8 warps (4x2), 32x32 warp tile, BK=32, 3-stage cp.async.
// Segment select: seg = rowBase >> segShift picks B (bStride) and bias.
// ---------------------------------------------------------------------------
__global__ __launch_bounds__(256, 2) void gemm_hmma(
    const __nv_bfloat16* __restrict__ A,
    const __nv_bfloat16* __restrict__ B, size_t bStride,
    const float* __restrict__ bias, int biasStride,
    float* __restrict__ C, int segShift)
{
    __shared__ __align__(1024) char smem[STAGES * STAGE_BYTES];
    const int tid  = threadIdx.x;
    const int lane = tid & 31, wid = tid >> 5;
    const int wm = wid & 3, wn = wid >> 2;       // 4 x 2 warps
    const int rowBase = blockIdx.y * 128;
    const int colBase = blockIdx.x * 64;
    const int seg = rowBase >> segShift;
    const uint32_t sbase = smem_u32(smem);

    const __nv_bfloat16* Ag = A + (size_t)rowBase * GK2;
    const __nv_bfloat16* Bg = B + (size_t)seg * bStride + (size_t)colBase * GK2;
    const float* bp = bias + (size_t)seg * biasStride;

    const int lr = tid >> 2;      // load row (A: lr and lr+64; B: lr)
    const int ac = tid & 3;       // 16B chunk within 64B row

    float acc[2][4][4];
    #pragma unroll
    for (int mi = 0; mi < 2; mi++)
        #pragma unroll
        for (int j = 0; j < 4; j++)
            #pragma unroll
            for (int e = 0; e < 4; e++) acc[mi][j][e] = 0.0f;

    #define KOFF_A(ks) (((ks) >= 2*SEGSTEP ? 768 : 0) + ((ks) % SEGSTEP) * BK)
    #define KOFF_B(ks) ((((ks) >= SEGSTEP && (ks) < 2*SEGSTEP) ? 768 : 0) + ((ks) % SEGSTEP) * BK)

    // prologue: stages 0,1
    #pragma unroll
    for (int s = 0; s < STAGES - 1; s++) {
        const int ka = KOFF_A(s), kb = KOFF_B(s);
        const uint32_t sa = sbase + s * STAGE_BYTES;
        const uint32_t sb = sa + SM_ABYTES;
        cp16(sa + swz(lr, ac),      Ag + (size_t)lr * GK2 + ka + ac * 8);
        cp16(sa + swz(lr + 64, ac), Ag + (size_t)(lr + 64) * GK2 + ka + ac * 8);
        cp16(sb + swz(lr, ac),      Bg + (size_t)lr * GK2 + kb + ac * 8);
        CP_COMMIT();
    }

    const int flr = lane & 15;
    const int flc = lane >> 4;

    for (int ks = 0; ks < NKSTEP; ks++) {
        CP_WAIT1();
        __syncthreads();

        if (ks + STAGES - 1 < NKSTEP) {
            const int kn = ks + STAGES - 1;
            const int s  = kn % STAGES;
            const int ka = KOFF_A(kn), kb = KOFF_B(kn);
            const uint32_t sa = sbase + s * STAGE_BYTES;
            const uint32_t sb = sa + SM_ABYTES;
            cp16(sa + swz(lr, ac),      Ag + (size_t)lr * GK2 + ka + ac * 8);
            cp16(sa + swz(lr + 64, ac), Ag + (size_t)(lr + 64) * GK2 + ka + ac * 8);
            cp16(sb + swz(lr, ac),      Bg + (size_t)lr * GK2 + kb + ac * 8);
            CP_COMMIT();
        }

        const uint32_t sa = sbase + (ks % STAGES) * STAGE_BYTES;
        const uint32_t sb = sa + SM_ABYTES;
        #pragma unroll
        for (int kh = 0; kh < 2; kh++) {
            uint32_t afr[2][4], bfr[2][4];
            const int cc = kh * 2 + flc;
            #pragma unroll
            for (int mi = 0; mi < 2; mi++)
                ldsm4(afr[mi], sa + swz(wm * 32 + mi * 16 + flr, cc));
            #pragma unroll
            for (int ni = 0; ni < 2; ni++)
                ldsm4(bfr[ni], sb + swz(wn * 32 + ni * 16 + flr, cc));
            #pragma unroll
            for (int mi = 0; mi < 2; mi++)
                #pragma unroll
                for (int ni = 0; ni < 2; ni++)
                    #pragma unroll
                    for (int nn = 0; nn < 2; nn++)
                        mma16816(acc[mi][ni * 2 + nn], afr[mi],
                                 bfr[ni][nn], bfr[ni][nn + 2]);
        }
    }

    // epilogue: +bias, write fp32
    #pragma unroll
    for (int mi = 0; mi < 2; mi++) {
        const int row0 = rowBase + wm * 32 + mi * 16 + (lane >> 2);
        #pragma unroll
        for (int j = 0; j < 4; j++) {
            const int col = colBase + wn * 32 + j * 8 + (lane & 3) * 2;
            const float2 bv = *(const float2*)(bp + col);
            float2 o0, o1;
            o0.x = acc[mi][j][0] + bv.x; o0.y = acc[mi][j][1] + bv.y;
            o1.x = acc[mi][j][2] + bv.x; o1.y = acc[mi][j][3] + bv.y;
            *(float2*)(C + (size_t)row0 * D_MODEL + col) = o0;
            *(float2*)(C + (size_t)(row0 + 8) * D_MODEL + col) = o1;
        }
    }
}

// ---------------------------------------------------------------------------
// M = K^T V / sqrt(dk), per (b,h), chunked over t.
// Kp = g_KVp rows [0,4096), Vp = rows [4096,8192).
// ---------------------------------------------------------------------------
__global__ __launch_bounds__(256) void kv_partial_kernel()
{
    const int chunk = blockIdx.x;
    const int bh    = blockIdx.y;
    const int b = bh / NHEAD, h = bh % NHEAD;
    const int tid = threadIdx.x;
    const int tx = tid & 15, ty = tid >> 4;

    __shared__ float ks[8][64];
    __shared__ float vs[8][64];

    const int rowBase = b * SEQ + chunk * CHUNK_T;
    const int colOff  = h * DK;

    const int li = tid * 2;
    const int lr = li >> 6;
    const int lc = li & 63;

    float acc[4][4];
    #pragma unroll
    for (int i = 0; i < 4; i++)
        #pragma unroll
        for (int j = 0; j < 4; j++) acc[i][j] = 0.0f;

    const float* Kp = g_KVp;
    const float* Vp = g_KVp + (size_t)NTOK * D_MODEL;

    for (int tt = 0; tt < CHUNK_T; tt += 8) {
        const size_t off = (size_t)(rowBase + tt + lr) * D_MODEL + colOff + lc;
        const float2 k2 = *(const float2*)(Kp + off);
        const float2 v2 = *(const float2*)(Vp + off);
        __syncthreads();
        ks[lr][lc] = k2.x; ks[lr][lc + 1] = k2.y;
        vs[lr][lc] = v2.x; vs[lr][lc + 1] = v2.y;
        __syncthreads();

        #pragma unroll
        for (int r = 0; r < 8; r++) {
            const float a0 = ks[r][ty * 4 + 0];
            const float a1 = ks[r][ty * 4 + 1];
            const float a2 = ks[r][ty * 4 + 2];
            const float a3 = ks[r][ty * 4 + 3];
            const float b0 = vs[r][tx * 4 + 0];
            const float b1 = vs[r][tx * 4 + 1];
            const float b2 = vs[r][tx * 4 + 2];
            const float b3 = vs[r][tx * 4 + 3];
            acc[0][0] += a0 * b0; acc[0][1] += a0 * b1; acc[0][2] += a0 * b2; acc[0][3] += a0 * b3;
            acc[1][0] += a1 * b0; acc[1][1] += a1 * b1; acc[1][2] += a1 * b2; acc[1][3] += a1 * b3;
            acc[2][0] += a2 * b0; acc[2][1] += a2 * b1; acc[2][2] += a2 * b2; acc[2][3] += a2 * b3;
            acc[3][0] += a3 * b0; acc[3][1] += a3 * b1; acc[3][2] += a3 * b2; acc[3][3] += a3 * b3;
        }
    }

    float* mp = g_Mpart + ((size_t)bh * NCHUNK + chunk) * DK * DK;
    #pragma unroll
    for (int i = 0; i < 4; i++)
        #pragma unroll
        for (int j = 0; j < 4; j++)
            mp[(ty * 4 + i) * DK + tx * 4 + j] = acc[i][j];
}

__global__ __launch_bounds__(256) void kv_reduce_kernel()
{
    const int bh = blockIdx.x;
    for (int e = threadIdx.x; e < DK * DK; e += 256) {
        float s = 0.0f;
        #pragma unroll
        for (int c = 0; c < NCHUNK; c++)
            s += g_Mpart[((size_t)bh * NCHUNK + c) * DK * DK + e];
        g_M[(size_t)bh * DK * DK + e] = s * SCALE;
    }
}

// ---------------------------------------------------------------------------
// T_b[i][h*64+j] = sum_l W_q[i][h*64+l] * M_b[h][l][j].  Grid (24 bh, 12 itiles)
// ---------------------------------------------------------------------------
__global__ __launch_bounds__(256) void t_kernel(const float* __restrict__ w_q)
{
    const int bh = blockIdx.x;
    const int b = bh / NHEAD, h = bh % NHEAD;
    const int i0 = blockIdx.y * 64;
    const int tid = threadIdx.x;

    __shared__ float Ms[DK][DK];
    __shared__ float Ws[DK][DK];

    for (int i = tid; i < DK * DK; i += 256) {
        Ms[i >> 6][i & 63] = g_M[(size_t)bh * DK * DK + i];
        Ws[i >> 6][i & 63] = w_q[(size_t)(i0 + (i >> 6)) * D_MODEL + h * DK + (i & 63)];
    }
    __syncthreads();

    const int c  = tid & 63;
    const int rg = tid >> 6;
    for (int r = rg * 16; r < rg * 16 + 16; r++) {
        float acc = 0.0f;
        #pragma unroll 16
        for (int l = 0; l < DK; l++) acc += Ws[r][l] * Ms[l][c];
        g_T[(size_t)(b * D_MODEL + i0 + r) * D_MODEL + h * DK + c] = acc;
    }
}

// cvec_b = b_o + (b_q · BD(M_b)) @ W_o.  Grid (2, 6): 128 m-cols per block,
// coalesced w_o reads, n-range split across two thread halves.
__global__ __launch_bounds__(256) void cvec_kernel(
    const float* __restrict__ b_q, const float* __restrict__ w_o,
    const float* __restrict__ b_o)
{
    const int b  = blockIdx.x;
    const int m0 = blockIdx.y * 128;
    const int tid = threadIdx.x;
    __shared__ float bqM[D_MODEL];
    __shared__ float part[128];

    for (int n = tid; n < D_MODEL; n += 256) {
        const int h = n >> 6, j = n & 63;
        float s = 0.0f;
        #pragma unroll 16
        for (int i = 0; i < DK; i++)
            s += b_q[h * DK + i] * g_M[(size_t)(b * NHEAD + h) * DK * DK + i * DK + j];
        bqM[n] = s;
    }
    __syncthreads();

    const int m    = m0 + (tid & 127);
    const int half = tid >> 7;
    float s = 0.0f;
    for (int n = half * 384; n < half * 384 + 384; n++)
        s += bqM[n] * w_o[(size_t)n * D_MODEL + m];
    if (half) part[tid & 127] = s;
    __syncthreads();
    if (!half)
        g_cvec[b * D_MODEL + m] = s + part[tid & 127] + b_o[m];
}

// ---------------------------------------------------------------------------
// Exact mask handling, applied directly to out (projected through W_o).
// All-ones mask => pure scan, no work.
// ---------------------------------------------------------------------------
__global__ __launch_bounds__(256) void mask_correction_kernel(
    const int* __restrict__ mask, const float* __restrict__ q,
    const float* __restrict__ w_q, const float* __restrict__ b_q,
    const float* __restrict__ w_o, float* __restrict__ out)
{
    const int s = blockIdx.x;
    const int* mrow = mask + (size_t)s * SEQ;
    const float* Kp = g_KVp;
    const float* Vp = g_KVp + (size_t)NTOK * D_MODEL;
    for (int t = threadIdx.x; t < SEQ; t += 256) {
        if (mrow[t] == 0) {
            for (int b = 0; b < BATCH; b++) {
                const float* qrow = q + (size_t)(b * SEQ + s) * D_MODEL;
                const float* krow = Kp + (size_t)(b * SEQ + t) * D_MODEL;
                const float* vrow = Vp + (size_t)(b * SEQ + t) * D_MODEL;
                float* orow = out + (size_t)(b * SEQ + s) * D_MODEL;
                for (int h = 0; h < NHEAD; h++) {
                    float raw = 0.0f;
                    for (int l = 0; l < DK; l++) {
                        float qp = b_q[h * DK + l];
                        for (int i = 0; i < D_MODEL; i++)
                            qp += qrow[i] * w_q[(size_t)i * D_MODEL + h * DK + l];
                        raw += qp * krow[h * DK + l];
                    }
                    const float delta = NEGV - raw * SCALE;
                    for (int m = 0; m < D_MODEL; m++) {
                        float pv = 0.0f;
                        for (int j = 0; j < DK; j++)
                            pv += vrow[h * DK + j] * w_o[(size_t)(h * DK + j) * D_MODEL + m];
                        atomicAdd(&orow[m], delta * pv);
                    }
                }
            }
        }
    }
}

// ---------------------------------------------------------------------------
extern "C" void kernel_launch(void* const* d_in, const int* in_sizes, int n_in,
                              void* d_out, int out_size)
{
    const float* q    = (const float*)d_in[0];
    const float* k    = (const float*)d_in[1];
    const float* v    = (const float*)d_in[2];
    const int*   mask = (const int*)  d_in[3];
    const float* w_q  = (const float*)d_in[4];
    const float* b_q  = (const float*)d_in[5];
    const float* w_k  = (const float*)d_in[6];
    const float* b_k  = (const float*)d_in[7];
    const float* w_v  = (const float*)d_in[8];
    const float* b_v  = (const float*)d_in[9];
    const float* w_o  = (const float*)d_in[10];
    const float* b_o  = (const float*)d_in[11];
    float* out = (float*)d_out;

    float *KVp, *T, *G, *cvec, *zero, *biasKV;
    __nv_bfloat16 *Qext, *Aext, *Text, *Wext, *Gext;
    cudaGetSymbolAddress((void**)&KVp,    g_KVp);
    cudaGetSymbolAddress((void**)&T,      g_T);
    cudaGetSymbolAddress((void**)&G,      g_G);
    cudaGetSymbolAddress((void**)&cvec,   g_cvec);
    cudaGetSymbolAddress((void**)&zero,   g_zero);
    cudaGetSymbolAddress((void**)&biasKV, g_biasKV);
    cudaGetSymbolAddress((void**)&Qext,   g_Qext);
    cudaGetSymbolAddress((void**)&Aext,   g_Aext);
    cudaGetSymbolAddress((void**)&Text,   g_Text);
    cudaGetSymbolAddress((void**)&Wext,   g_Wext);
    cudaGetSymbolAddress((void**)&Gext,   g_Gext);

    const int actTotal = NTOK * D_MODEL;
    const int actBlocks = (actTotal + 255) / 256;
    const int tTotal = 2 * D_MODEL * D_MODEL;
    const int tBlocks = (tTotal + 255) / 256;
    const dim3 cwg(D_MODEL / 32, D_MODEL / 32, 1);        // (24,24)
    const dim3 cwg2(D_MODEL / 32, D_MODEL / 32, 2);       // batched
    const dim3 ggKV(D_MODEL / 64, 2 * NTOK / 128);        // (12, 64)
    const dim3 ggBig(D_MODEL / 64, NTOK / 128);           // (12, 32)
    const dim3 ggG(D_MODEL / 64, 2 * D_MODEL / 128);      // (12, 12)

    // --- merged K+V projection: rows 0-4095 = k@Wk, 4096-8191 = v@Wv
    convert_w<<<cwg, 256>>>(w_k, Wext);
    convert_w<<<cwg, 256>>>(w_v, Wext + (size_t)D_MODEL * GK2);
    convert_act<<<actBlocks, 256>>>(k, Aext, actTotal);
    convert_act<<<actBlocks, 256>>>(v, Aext + (size_t)NTOK * GK2, actTotal);
    cudaMemcpyAsync(biasKV,           b_k, D_MODEL * sizeof(float), cudaMemcpyDeviceToDevice);
    cudaMemcpyAsync(biasKV + D_MODEL, b_v, D_MODEL * sizeof(float), cudaMemcpyDeviceToDevice);
    gemm_hmma<<<ggKV, 256>>>(Aext, Wext, (size_t)D_MODEL * GK2,
                             biasKV, D_MODEL, KVp, 12);

    // q conversion (independent; sits in the stream bubble)
    convert_act<<<actBlocks, 256>>>(q, Qext, actTotal);

    // --- M = K^T V / sqrt(dk)
    kv_partial_kernel<<<dim3(NCHUNK, BHTOT), 256>>>();
    kv_reduce_kernel<<<BHTOT, 256>>>();

    // --- T_b = W_q * BD(M_b);  G_b = T_b @ W_o
    t_kernel<<<dim3(BHTOT, D_MODEL / 64), 256>>>(w_q);
    convert_act<<<tBlocks, 256>>>(T, Text, tTotal);
    convert_w<<<cwg, 256>>>(w_o, Wext);
    gemm_hmma<<<ggG, 256>>>(Text, Wext, 0, zero, 0, G, 30);

    // --- Gext (both batches, one launch) + cvec
    convert_w<<<cwg2, 256>>>(G, Gext);
    cvec_kernel<<<dim3(BATCH, D_MODEL / 128), 256>>>(b_q, w_o, b_o);

    // --- out[b] = q[b] @ G_b + cvec_b
    gemm_hmma<<<ggBig, 256>>>(Qext, Gext, (size_t)D_MODEL * GK2,
                              cvec, D_MODEL, out, 11);

    // exact mask handling (no-op for all-ones mask)
    mask_correction_kernel<<<SEQ, 256>>>(mask, q, w_q, b_q, w_o, out);
}